// round 7
// baseline (speedup 1.0000x reference)
#include <cuda_runtime.h>
#include <cuda_bf16.h>

#define NPTS 4096
#define NF   (NPTS - 2)
#define NFPAD 4104            // padded frame count, multiple of 6
#define NPAD  (NFPAD - NF)    // 10 pad frames
#define EPSF 1e-8f
#define LT   256
#define PT_CHUNK 2048
#define NGROUPS (NFPAD / 6)   // 684 groups of 6 frames
#define NBLK (NGROUPS * 2)    // x2 point chunks = 1368 blocks

typedef unsigned long long u64;

// Scratch (device globals only — allocations forbidden)
// Point data pre-duplicated for f32x2: rows 0..2 = (-p,-p).{x,y,z}, 3..5 = (q,q).{x,y,z}
__device__ __align__(16) u64 g_pd[6][NPTS];
// Fused frame constants, SoA over frames (padded to NFPAD):
// k=0..8: M = Rp^T * Rt (row-major), k=9..11: c = op - M*ot
__device__ __align__(16) float g_fc[12][NFPAD];
__device__ double g_acc;
__device__ unsigned g_tick;

__device__ __forceinline__ float rsqrt_fast(float x) {
    float y; asm("rsqrt.approx.f32 %0, %1;" : "=f"(y) : "f"(x)); return y;
}
__device__ __forceinline__ float sqrt_fast(float x) {
    float y; asm("sqrt.approx.f32 %0, %1;" : "=f"(y) : "f"(x)); return y;
}
__device__ __forceinline__ u64 dupf(float a) {
    u64 r; asm("mov.b64 %0, {%1, %1};" : "=l"(r) : "f"(a)); return r;
}
__device__ __forceinline__ u64 ffma2(u64 a, u64 b, u64 c) {
    u64 d; asm("fma.rn.f32x2 %0, %1, %2, %3;" : "=l"(d) : "l"(a), "l"(b), "l"(c));
    return d;
}
__device__ __forceinline__ u64 fadd2(u64 a, u64 b) {
    u64 d; asm("add.rn.f32x2 %0, %1, %2;" : "=l"(d) : "l"(a), "l"(b));
    return d;
}
__device__ __forceinline__ void unpk(u64 v, float& lo, float& hi) {
    asm("mov.b64 {%0, %1}, %2;" : "=f"(lo), "=f"(hi) : "l"(v));
}

// ss = |M*q + c - p|^2 + eps for one point against one packed frame-pair
__device__ __forceinline__ u64 pair_ss(const u64* __restrict__ A,
                                       u64 U, u64 V, u64 W,
                                       u64 NX, u64 NY, u64 NZ, u64 eps2) {
    u64 dx = ffma2(A[0], U, ffma2(A[1], V, ffma2(A[2], W, fadd2(A[9],  NX))));
    u64 dy = ffma2(A[3], U, ffma2(A[4], V, ffma2(A[5], W, fadd2(A[10], NY))));
    u64 dz = ffma2(A[6], U, ffma2(A[7], V, ffma2(A[8], W, fadd2(A[11], NZ))));
    return ffma2(dx, dx, ffma2(dy, dy, ffma2(dz, dz, eps2)));
}

__device__ __forceinline__ void build_frame(const float* __restrict__ c, int i,
                                            float* __restrict__ R, float* __restrict__ o) {
    float ox = c[3*i+3], oy = c[3*i+4], oz = c[3*i+5];
    float ax = c[3*i+6] - ox, ay = c[3*i+7] - oy, az = c[3*i+8] - oz;
    float i1 = rsqrt_fast(ax*ax + ay*ay + az*az);
    ax *= i1; ay *= i1; az *= i1;
    float bx = c[3*i] - ox, by = c[3*i+1] - oy, bz = c[3*i+2] - oz;
    float d = bx*ax + by*ay + bz*az;
    bx -= d*ax; by -= d*ay; bz -= d*az;
    float i2 = rsqrt_fast(bx*bx + by*by + bz*bz);
    bx *= i2; by *= i2; bz *= i2;
    R[0]=ax; R[1]=ay; R[2]=az;
    R[3]=bx; R[4]=by; R[5]=bz;
    R[6]=ay*bz - az*by; R[7]=az*bx - ax*bz; R[8]=ax*by - ay*bx;
    o[0]=ox; o[1]=oy; o[2]=oz;
}

__global__ void prep_kernel(const float* __restrict__ pred, const float* __restrict__ tru) {
    int i = blockIdx.x * blockDim.x + threadIdx.x;
    if (i == 0) g_acc = 0.0;
    if (i < NPTS) {
        g_pd[0][i] = dupf(-pred[3*i]);
        g_pd[1][i] = dupf(-pred[3*i+1]);
        g_pd[2][i] = dupf(-pred[3*i+2]);
        g_pd[3][i] = dupf(tru[3*i]);
        g_pd[4][i] = dupf(tru[3*i+1]);
        g_pd[5][i] = dupf(tru[3*i+2]);
    }
    if (i < NF) {
        float Rp[9], op[3], Rt[9], ot[3];
        build_frame(pred, i, Rp, op);
        build_frame(tru,  i, Rt, ot);
        float M[9];
        #pragma unroll
        for (int r = 0; r < 3; r++)
            #pragma unroll
            for (int cc = 0; cc < 3; cc++)
                M[3*r+cc] = Rp[r]*Rt[cc] + Rp[3+r]*Rt[3+cc] + Rp[6+r]*Rt[6+cc];
        #pragma unroll
        for (int k = 0; k < 9; k++) g_fc[k][i] = M[k];
        #pragma unroll
        for (int r = 0; r < 3; r++)
            g_fc[9 + r][i] = op[r] - (M[3*r]*ot[0] + M[3*r+1]*ot[1] + M[3*r+2]*ot[2]);
    } else if (i < NFPAD) {
        // Pad frames: dist clamps to exactly 10.0; removed analytically at the end.
        #pragma unroll
        for (int k = 0; k < 12; k++) g_fc[k][i] = 0.0f;
        g_fc[9][i] = 1e6f;
    }
}

// Each block: 6 frames (three f32x2 frame-pairs) x 2048 points, 2 points/thread/iter.
__global__ void __launch_bounds__(LT, 2) loss_kernel(float* __restrict__ out) {
    const int f  = (blockIdx.x >> 1) * 6;
    const int n0 = (blockIdx.x & 1) * PT_CHUNK;

    u64 A[12], B[12], C[12];
    #pragma unroll
    for (int k = 0; k < 12; k++) {
        const float* fk = &g_fc[k][f];
        A[k] = *(const u64*)(fk);
        B[k] = *(const u64*)(fk + 2);
        C[k] = *(const u64*)(fk + 4);
    }
    const u64 eps2 = dupf(EPSF);

    float s0 = 0.0f, s1 = 0.0f, s2 = 0.0f, s3 = 0.0f;

    // 2 consecutive points per thread per iter via 16B loads of the dup'd array.
    const char* __restrict__ base = (const char*)&g_pd[0][n0 + 2 * threadIdx.x];

    #pragma unroll
    for (int it = 0; it < PT_CHUNK / (2 * LT); it++, base += 2 * LT * sizeof(u64)) {
        ulonglong2 nx = *(const ulonglong2*)(base + 0 * NPTS * sizeof(u64));
        ulonglong2 ny = *(const ulonglong2*)(base + 1 * NPTS * sizeof(u64));
        ulonglong2 nz = *(const ulonglong2*)(base + 2 * NPTS * sizeof(u64));
        ulonglong2 qu = *(const ulonglong2*)(base + 3 * NPTS * sizeof(u64));
        ulonglong2 qv = *(const ulonglong2*)(base + 4 * NPTS * sizeof(u64));
        ulonglong2 qw = *(const ulonglong2*)(base + 5 * NPTS * sizeof(u64));

        u64 ss[6];
        ss[0] = pair_ss(A, qu.x, qv.x, qw.x, nx.x, ny.x, nz.x, eps2);
        ss[1] = pair_ss(B, qu.x, qv.x, qw.x, nx.x, ny.x, nz.x, eps2);
        ss[2] = pair_ss(C, qu.x, qv.x, qw.x, nx.x, ny.x, nz.x, eps2);
        ss[3] = pair_ss(A, qu.y, qv.y, qw.y, nx.y, ny.y, nz.y, eps2);
        ss[4] = pair_ss(B, qu.y, qv.y, qw.y, nx.y, ny.y, nz.y, eps2);
        ss[5] = pair_ss(C, qu.y, qv.y, qw.y, nx.y, ny.y, nz.y, eps2);

        #pragma unroll
        for (int k = 0; k < 6; k += 2) {
            float v0, v1, v2, v3;
            unpk(ss[k],     v0, v1);
            unpk(ss[k + 1], v2, v3);
            s0 += fminf(sqrt_fast(v0), 10.0f);
            s1 += fminf(sqrt_fast(v1), 10.0f);
            s2 += fminf(sqrt_fast(v2), 10.0f);
            s3 += fminf(sqrt_fast(v3), 10.0f);
        }
    }

    float sum = (s0 + s1) + (s2 + s3);
    #pragma unroll
    for (int o = 16; o > 0; o >>= 1)
        sum += __shfl_down_sync(0xffffffffu, sum, o);

    __shared__ float wsum[LT / 32];
    int lane = threadIdx.x & 31;
    int wid  = threadIdx.x >> 5;
    if (lane == 0) wsum[wid] = sum;
    __syncthreads();
    if (threadIdx.x == 0) {
        float v = 0.0f;
        #pragma unroll
        for (int w = 0; w < LT / 32; w++) v += wsum[w];
        atomicAdd(&g_acc, (double)v);
        __threadfence();
        unsigned t = atomicAdd(&g_tick, 1u);
        if (t == (unsigned)(gridDim.x - 1)) {
            double total = *((volatile double*)&g_acc);
            total -= (double)NPAD * (double)NPTS * 10.0;   // pad frames: exactly 10 each
            out[0] = (float)(total / ((double)NF * (double)NPTS) / 10.0);
            g_tick = 0u;  // reset for next graph replay
        }
    }
}

extern "C" void kernel_launch(void* const* d_in, const int* in_sizes, int n_in,
                              void* d_out, int out_size) {
    const float* pred = (const float*)d_in[0];
    const float* tru  = (const float*)d_in[1];
    float* out = (float*)d_out;

    prep_kernel<<<(NFPAD + 255) / 256, 256>>>(pred, tru);
    loss_kernel<<<NBLK, LT>>>(out);
}